// round 16
// baseline (speedup 1.0000x reference)
#include <cuda_runtime.h>
#include <cuda_bf16.h>
#include <cstdint>

#define SEQ    16384
#define CDIM   128
#define KDIM   64
#define BDIM   16
#define NCHUNK 16
#define STILE  128
#define TPB    256
#define NTILE  ((SEQ / NCHUNK) / STILE)   // 8

// smem byte offsets (double-buffered XT)
#define SM_X2P  0                              // x2 partials [8][128] f32 (4096)
#define SM_ATP  4096                           // aAcc partials [8][64] f32 (2048)
#define SM_C4   6144                           // float4[64] per-k consts (1024)
#define SM_XT0  7168                           // X^T[c][s] bf16 128x136 (34816)
#define SM_XT1  41984                          // second buffer (34816)
#define SM_CW   76800                          // CW[k][c] bf16 64x136 (17408)
#define SM_AT   94208                          // a[s][k] bf16 128x72 (18432)
#define SMEM_BYTES 112640                      // x2 CTAs = 225,280 <= 231,424
#define XTSZ    34816

// deterministic scratch
__device__ float g_epart[(long)NCHUNK * BDIM * KDIM * CDIM];
__device__ float g_Apart[NCHUNK * BDIM * KDIM];
__device__ float g_ecorr[BDIM * KDIM * CDIM];
__device__ float g_gk[KDIM];
__device__ float g_hk[KDIM];
__device__ float g_en[BDIM * CDIM];
__device__ float g_scale[BDIM * CDIM];
// precomputed operands (prep kernel)
__device__ float4 g_cwb4[KDIM * 272 / 16];     // CW bf16, 272B-stride layout
__device__ float4 g_c4g[KDIM];                 // (sk, sk*cw2, -2sk, 0)

__device__ __forceinline__ uint32_t smem_u32(const void* p) {
    uint32_t a;
    asm("{ .reg .u64 t; cvta.to.shared.u64 t, %1; cvt.u32.u64 %0, t; }" : "=r"(a) : "l"(p));
    return a;
}
__device__ __forceinline__ uint32_t bf2(float lo, float hi) {   // [15:0]=bf16(lo), [31:16]=bf16(hi)
    uint32_t r;
    asm("cvt.rn.bf16x2.f32 %0, %1, %2;" : "=r"(r) : "f"(hi), "f"(lo));
    return r;
}
__device__ __forceinline__ void ldm4(uint32_t* r, uint32_t a) {
    asm volatile("ldmatrix.sync.aligned.m8n8.x4.shared.b16 {%0,%1,%2,%3}, [%4];"
                 : "=r"(r[0]), "=r"(r[1]), "=r"(r[2]), "=r"(r[3]) : "r"(a));
}
__device__ __forceinline__ void ldm4t(uint32_t* r, uint32_t a) {
    asm volatile("ldmatrix.sync.aligned.m8n8.x4.trans.shared.b16 {%0,%1,%2,%3}, [%4];"
                 : "=r"(r[0]), "=r"(r[1]), "=r"(r[2]), "=r"(r[3]) : "r"(a));
}
__device__ __forceinline__ void mma16816(float* d, const uint32_t* a, const uint32_t* b) {
    asm volatile("mma.sync.aligned.m16n8k16.row.col.f32.bf16.bf16.f32 "
                 "{%0,%1,%2,%3}, {%4,%5,%6,%7}, {%8,%9}, {%0,%1,%2,%3};"
                 : "+f"(d[0]), "+f"(d[1]), "+f"(d[2]), "+f"(d[3])
                 : "r"(a[0]), "r"(a[1]), "r"(a[2]), "r"(a[3]), "r"(b[0]), "r"(b[1]));
}

// ---------------------------------------------------------------------------
// Kernel P: one-time CW conversion + per-k constants (block = one k row)
// ---------------------------------------------------------------------------
__global__ void encnet_prep(const float* __restrict__ cw, const float* __restrict__ smth)
{
    const int k = blockIdx.x, tid = threadIdx.x;     // 128 threads
    __shared__ float red[128];
    float v = __ldg(cw + k * CDIM + tid);
    __nv_bfloat16* row = (__nv_bfloat16*)((unsigned char*)g_cwb4 + k * 272);
    row[tid] = __float2bfloat16(v);
    if (tid < 8) row[128 + tid] = __float2bfloat16(0.f);   // zero pad cols 128..135
    red[tid] = v * v;
    __syncthreads();
    for (int o = 64; o > 0; o >>= 1) { if (tid < o) red[tid] += red[tid + o]; __syncthreads(); }
    if (tid == 0) {
        float s = __ldg(smth + k);
        g_c4g[k] = make_float4(s, s * red[0], -2.f * s, 0.f);
    }
}

// ---------------------------------------------------------------------------
// Kernel A: cross GEMM + softmax + aggregation GEMM; double-buffered XT,
// 2 barriers/tile. 2 CTAs/SM.
// ---------------------------------------------------------------------------
__global__ void __launch_bounds__(TPB, 2) encnet_main(
    const float* __restrict__ x)
{
    extern __shared__ unsigned char smem[];
    const uint32_t sb = smem_u32(smem);
    float*  x2p = (float*)(smem + SM_X2P);
    float*  atp = (float*)(smem + SM_ATP);
    float4* c4  = (float4*)(smem + SM_C4);

    const int tid = threadIdx.x, lane = tid & 31, w = tid >> 5;
    const int chunk = blockIdx.x, b = blockIdx.y;
    const float* xg = x + (long)b * CDIM * SEQ + chunk * (SEQ / NCHUNK);

    // copy precomputed CW (bf16, final layout) + c4 into smem
    {
        float4* dst = (float4*)(smem + SM_CW);
        #pragma unroll
        for (int i = 0; i < 5; i++) {
            int idx = tid + i * TPB;
            if (idx < KDIM * 272 / 16) dst[idx] = __ldg(g_cwb4 + idx);
        }
        if (tid < KDIM) c4[tid] = __ldg(g_c4g + tid);
    }

    // ldmatrix base addresses (XT-relative; add buffer offset per tile)
    const int m0 = 16 * w;
    const uint32_t a1rel = sb + SM_XT0 +
        (uint32_t)((((lane >> 4) << 3) + (lane & 7)) * 272 + (m0 + (lane & 8)) * 2);
    const uint32_t a2rel = sb + SM_XT0 +
        (uint32_t)((m0 + (lane & 15)) * 272 + (lane >> 4) * 16);
    const uint32_t bcw4 = sb + SM_CW +
        (uint32_t)((lane & 7) * 272 + ((lane >> 3) & 1) * 16 + (lane >> 4) * 2176);
    const uint32_t bat4 = sb + SM_AT +
        (uint32_t)((lane & 15) * 144 + (lane >> 4) * 16);

    float acc2[8][4];
    #pragma unroll
    for (int i = 0; i < 8; i++)
        { acc2[i][0] = acc2[i][1] = acc2[i][2] = acc2[i][3] = 0.f; }
    float aAcc = 0.f;

    __syncthreads();   // CW/c4 ready

    for (int t = 0; t < NTILE; t++) {
        const uint32_t xoff = (uint32_t)(t & 1) * XTSZ;

        // ---- convert: direct LDG -> bf16 XT[t&1]; x2 partials (overlaps prev GEMM2) ----
        {
            float4 x2a = make_float4(0.f, 0.f, 0.f, 0.f);
            const float* xt0 = xg + t * STILE;
            unsigned char* xtb = smem + SM_XT0 + xoff;
            #pragma unroll
            for (int it = 0; it < 16; it++) {
                int cc = w + it * 8;                       // warp = full row
                float4 v = __ldg((const float4*)(xt0 + (long)cc * SEQ) + lane);
                x2a.x = fmaf(v.x, v.x, x2a.x);
                x2a.y = fmaf(v.y, v.y, x2a.y);
                x2a.z = fmaf(v.z, v.z, x2a.z);
                x2a.w = fmaf(v.w, v.w, x2a.w);
                uint32_t h0 = bf2(v.x, v.y), h1 = bf2(v.z, v.w);
                *(uint2*)(xtb + cc * 272 + lane * 8) = make_uint2(h0, h1);
            }
            *(float4*)(x2p + w * 128 + lane * 4) = x2a;
        }
        __syncthreads();   // XT[t&1] + x2p ready (also: all GEMM2(t-1) reads done)

        // ---- GEMM1: cross[s=128, k=64] = Xh . CW^T ----
        float acc1[8][4];
        #pragma unroll
        for (int i = 0; i < 8; i++)
            { acc1[i][0] = acc1[i][1] = acc1[i][2] = acc1[i][3] = 0.f; }
        {
            uint32_t aH[4], bb[4];
            #pragma unroll
            for (int kc = 0; kc < 8; kc++) {
                ldm4t(aH, a1rel + xoff + kc * 4352);      // 16 c-rows * 272B
                #pragma unroll
                for (int ntp = 0; ntp < 4; ntp++) {
                    ldm4(bb, bcw4 + ntp * 4352 + kc * 32);
                    mma16816(acc1[2 * ntp],     aH, bb);
                    mma16816(acc1[2 * ntp + 1], aH, bb + 2);
                }
            }
        }

        // ---- softmax on fragments (x2 summed from partials inline) ----
        {
            const int g = lane >> 2, q = lane & 3;
            const int s0r = m0 + g;
            float xa = 0.f, xb = 0.f;
            #pragma unroll
            for (int ww = 0; ww < 8; ww++) {
                xa += x2p[ww * 128 + s0r];
                xb += x2p[ww * 128 + s0r + 8];
            }
            float p0[16], p1[16];
            float mA = -3.4e38f, mB = -3.4e38f;
            #pragma unroll
            for (int nt = 0; nt < 8; nt++) {
                float4 cA = c4[8 * nt + 2 * q];
                float4 cB = c4[8 * nt + 2 * q + 1];
                p0[2*nt]   = fmaf(cA.z, acc1[nt][0], fmaf(cA.x, xa, cA.y));
                p0[2*nt+1] = fmaf(cB.z, acc1[nt][1], fmaf(cB.x, xa, cB.y));
                p1[2*nt]   = fmaf(cA.z, acc1[nt][2], fmaf(cA.x, xb, cA.y));
                p1[2*nt+1] = fmaf(cB.z, acc1[nt][3], fmaf(cB.x, xb, cB.y));
                mA = fmaxf(mA, fmaxf(p0[2*nt], p0[2*nt+1]));
                mB = fmaxf(mB, fmaxf(p1[2*nt], p1[2*nt+1]));
            }
            mA = fmaxf(mA, __shfl_xor_sync(0xffffffffu, mA, 1));
            mA = fmaxf(mA, __shfl_xor_sync(0xffffffffu, mA, 2));
            mB = fmaxf(mB, __shfl_xor_sync(0xffffffffu, mB, 1));
            mB = fmaxf(mB, __shfl_xor_sync(0xffffffffu, mB, 2));
            float sA = 0.f, sB = 0.f;
            #pragma unroll
            for (int j = 0; j < 16; j++) {
                p0[j] = __expf(p0[j] - mA); sA += p0[j];
                p1[j] = __expf(p1[j] - mB); sB += p1[j];
            }
            sA += __shfl_xor_sync(0xffffffffu, sA, 1);
            sA += __shfl_xor_sync(0xffffffffu, sA, 2);
            sB += __shfl_xor_sync(0xffffffffu, sB, 1);
            sB += __shfl_xor_sync(0xffffffffu, sB, 2);
            float iA = 1.f / sA, iB = 1.f / sB;
            #pragma unroll
            for (int nt = 0; nt < 8; nt++) {
                const int k0 = 8 * nt + 2 * q;
                float a00 = p0[2*nt] * iA, a01 = p0[2*nt+1] * iA;
                float a10 = p1[2*nt] * iB, a11 = p1[2*nt+1] * iB;
                *(uint32_t*)(smem + SM_AT + s0r * 144 + k0 * 2)       = bf2(a00, a01);
                *(uint32_t*)(smem + SM_AT + (s0r + 8) * 144 + k0 * 2) = bf2(a10, a11);
                // per-k partial sums over this warp's 16 s rows
                float v0 = a00 + a10, v1 = a01 + a11;
                v0 += __shfl_xor_sync(0xffffffffu, v0, 4);
                v1 += __shfl_xor_sync(0xffffffffu, v1, 4);
                v0 += __shfl_xor_sync(0xffffffffu, v0, 8);
                v1 += __shfl_xor_sync(0xffffffffu, v1, 8);
                v0 += __shfl_xor_sync(0xffffffffu, v0, 16);
                v1 += __shfl_xor_sync(0xffffffffu, v1, 16);
                if (g == 0) {
                    atp[w * 64 + k0]     = v0;
                    atp[w * 64 + k0 + 1] = v1;
                }
            }
        }
        __syncthreads();   // AT + atp ready

        if (tid < KDIM) {
            float a = 0.f;
            #pragma unroll
            for (int ww = 0; ww < 8; ww++) a += atp[ww * 64 + tid];
            aAcc += a;
        }

        // ---- GEMM2: e[c=128, k=64] += Xh . a  (next convert overlaps this) ----
        {
            uint32_t aH[4], bb[4];
            #pragma unroll
            for (int kc = 0; kc < 8; kc++) {
                ldm4(aH, a2rel + xoff + kc * 32);         // 16 s-elems * 2B
                #pragma unroll
                for (int ntp = 0; ntp < 4; ntp++) {
                    ldm4t(bb, bat4 + kc * 2304 + ntp * 32);
                    mma16816(acc2[2 * ntp],     aH, bb);
                    mma16816(acc2[2 * ntp + 1], aH, bb + 2);
                }
            }
        }
        // no end-of-tile sync: XT double-buffered; AT/x2p hazards covered above
    }

    // ---- epilogue: write chunk partials ----
    {
        float* ep = g_epart + ((long)(chunk * BDIM + b) * KDIM) * CDIM;
        const int c0r = m0 + (lane >> 2), q = lane & 3;
        #pragma unroll
        for (int nt = 0; nt < 8; nt++) {
            int k0 = 8 * nt + 2 * q;
            ep[k0 * CDIM + c0r]           = acc2[nt][0];
            ep[(k0 + 1) * CDIM + c0r]     = acc2[nt][1];
            ep[k0 * CDIM + c0r + 8]       = acc2[nt][2];
            ep[(k0 + 1) * CDIM + c0r + 8] = acc2[nt][3];
        }
        if (tid < KDIM) g_Apart[(chunk * BDIM + b) * KDIM + tid] = aAcc;
    }
}

// ---------------------------------------------------------------------------
// Kernel B: reduce chunk partials, subtract A*cw, BN batch stats per k
// ---------------------------------------------------------------------------
__global__ void encnet_stats(const float* __restrict__ cw,
                             const float* __restrict__ bnw,
                             const float* __restrict__ bnb)
{
    const int k = blockIdx.x, tid = threadIdx.x;   // 256 threads
    __shared__ float Ab[BDIM];
    __shared__ float red[256];

    if (tid < BDIM) {
        float a = 0.f;
        #pragma unroll
        for (int ch = 0; ch < NCHUNK; ch++) a += g_Apart[(ch * BDIM + tid) * KDIM + k];
        Ab[tid] = a;
    }
    __syncthreads();

    float sum = 0.f, ss = 0.f;
    for (int i = tid; i < BDIM * CDIM; i += 256) {
        int bb = i >> 7, c = i & 127;
        float v = 0.f;
        #pragma unroll
        for (int ch = 0; ch < NCHUNK; ch++)
            v += g_epart[(((long)ch * BDIM + bb) * KDIM + k) * CDIM + c];
        v -= Ab[bb] * __ldg(cw + k * CDIM + c);
        g_ecorr[(bb * KDIM + k) * CDIM + c] = v;
        sum += v;
        ss = fmaf(v, v, ss);
    }
    red[tid] = sum; __syncthreads();
    for (int o = 128; o > 0; o >>= 1) { if (tid < o) red[tid] += red[tid + o]; __syncthreads(); }
    float tsum = red[0]; __syncthreads();
    red[tid] = ss; __syncthreads();
    for (int o = 128; o > 0; o >>= 1) { if (tid < o) red[tid] += red[tid + o]; __syncthreads(); }
    if (tid == 0) {
        const float n = (float)(BDIM * CDIM);
        float mean = tsum / n;
        float var = red[0] / n - mean * mean;
        float rstd = rsqrtf(var + 1e-5f);
        float g = rstd * __ldg(bnw + k);
        g_gk[k] = g;
        g_hk[k] = __ldg(bnb + k) - mean * g;
    }
}

// ---------------------------------------------------------------------------
// Kernel C1: en[b][c] = mean_k relu(bn(e))  -- wide grid (8 x 16) x 256
// ---------------------------------------------------------------------------
__global__ void encnet_fc1()
{
    const int cgrp = blockIdx.x, b = blockIdx.y;
    const int tid = threadIdx.x;
    const int cl = tid & 15, kg = tid >> 4;       // kg 0..15
    const int c = cgrp * 16 + cl;
    __shared__ float red[16][17];

    float acc = 0.f;
    const float* er = g_ecorr + ((long)b * KDIM + kg * 4) * CDIM + c;
    #pragma unroll
    for (int j = 0; j < 4; j++) {
        int k = kg * 4 + j;
        acc += fmaxf(fmaf(er[j * CDIM], __ldg(&g_gk[k]), __ldg(&g_hk[k])), 0.f);
    }
    red[kg][cl] = acc;
    __syncthreads();
    if (tid < 16) {
        float s = 0.f;
        #pragma unroll
        for (int j = 0; j < 16; j++) s += red[j][tid];
        g_en[b * CDIM + cgrp * 16 + tid] = s * (1.f / (float)KDIM);
    }
}

// ---------------------------------------------------------------------------
// Kernel C2: scale[b][cout] = sigmoid(en[b].w[cout] + bias) -- grid (128 x 16) x 128
// ---------------------------------------------------------------------------
__global__ void encnet_fc2(const float* __restrict__ fcw, const float* __restrict__ fcb)
{
    const int co = blockIdx.x, b = blockIdx.y, tid = threadIdx.x;
    __shared__ float red[128];
    red[tid] = g_en[b * CDIM + tid] * __ldg(fcw + co * CDIM + tid);
    __syncthreads();
    for (int o = 64; o > 0; o >>= 1) { if (tid < o) red[tid] += red[tid + o]; __syncthreads(); }
    if (tid == 0)
        g_scale[b * CDIM + co] = 1.f / (1.f + __expf(-(red[0] + __ldg(fcb + co))));
}

// ---------------------------------------------------------------------------
// Kernel D: out = x * scale  (memory bound; 8 independent iters -> MLP 8)
// ---------------------------------------------------------------------------
__global__ void encnet_scale(const float4* __restrict__ x4, float4* __restrict__ out4)
{
    const int i0 = blockIdx.x * 256 + threadIdx.x;   // grid 4096 x 256
    #pragma unroll
    for (int j = 0; j < 8; j++) {
        int i = i0 + j * (4096 * 256);
        float s = __ldg(&g_scale[i >> 12]);
        float4 v = __ldg(x4 + i);
        v.x *= s; v.y *= s; v.z *= s; v.w *= s;
        out4[i] = v;
    }
}

// ---------------------------------------------------------------------------
extern "C" void kernel_launch(void* const* d_in, const int* in_sizes, int n_in,
                              void* d_out, int out_size)
{
    const float* x    = (const float*)d_in[0];
    const float* cw   = (const float*)d_in[1];
    const float* smth = (const float*)d_in[2];
    const float* bnw  = (const float*)d_in[3];
    const float* bnb  = (const float*)d_in[4];
    const float* fcw  = (const float*)d_in[5];
    const float* fcb  = (const float*)d_in[6];
    float* out = (float*)d_out;

    cudaFuncSetAttribute(encnet_main, cudaFuncAttributeMaxDynamicSharedMemorySize, SMEM_BYTES);

    encnet_prep <<<KDIM, CDIM>>>(cw, smth);
    encnet_main <<<dim3(NCHUNK, BDIM), TPB, SMEM_BYTES>>>(x);
    encnet_stats<<<KDIM, 256>>>(cw, bnw, bnb);
    encnet_fc1  <<<dim3(8, BDIM), 256>>>();
    encnet_fc2  <<<dim3(CDIM, BDIM), 128>>>(fcw, fcb);
    encnet_scale<<<4096, 256>>>((const float4*)x, (float4*)out);
}

// round 17
// speedup vs baseline: 1.0772x; 1.0772x over previous
#include <cuda_runtime.h>
#include <cuda_bf16.h>
#include <cstdint>

#define SEQ    16384
#define CDIM   128
#define KDIM   64
#define BDIM   16
#define NCHUNK 16
#define STILE  128
#define TPB    256
#define NTILE  ((SEQ / NCHUNK) / STILE)   // 8

// smem byte offsets
#define SM_X2P  0                              // x2 partials [8][128] f32 (4096)
#define SM_ATP  4096                           // aAcc partials [8][64] f32 (2048)
#define SM_C4   6144                           // float4[64] per-k consts (1024)
#define SM_XTH  7168                           // X^T[c][s] bf16 128x136 (34816)
#define SM_CW   41984                          // CW[k][c] bf16 64x136 (17408)
#define SM_AT   59392                          // a[s][k] bf16 128x72 (18432)
#define SMEM_BYTES 77824                       // -> 2 CTAs/SM

// deterministic scratch
__device__ float g_epart[(long)NCHUNK * BDIM * KDIM * CDIM];
__device__ float g_Apart[NCHUNK * BDIM * KDIM];
__device__ float g_ecorr[BDIM * KDIM * CDIM];
__device__ float g_gk[KDIM];
__device__ float g_hk[KDIM];
__device__ float g_en[BDIM * CDIM];
__device__ float g_scale[BDIM * CDIM];
// precomputed operands (prep kernel)
__device__ float4 g_cwb4[KDIM * 272 / 16];     // CW bf16, 272B-stride layout
__device__ float4 g_c4g[KDIM];                 // (sk, sk*cw2, -2sk, 0)

__device__ __forceinline__ uint32_t smem_u32(const void* p) {
    uint32_t a;
    asm("{ .reg .u64 t; cvta.to.shared.u64 t, %1; cvt.u32.u64 %0, t; }" : "=r"(a) : "l"(p));
    return a;
}
__device__ __forceinline__ uint32_t bf2(float lo, float hi) {   // [15:0]=bf16(lo), [31:16]=bf16(hi)
    uint32_t r;
    asm("cvt.rn.bf16x2.f32 %0, %1, %2;" : "=r"(r) : "f"(hi), "f"(lo));
    return r;
}
__device__ __forceinline__ void ldm4(uint32_t* r, uint32_t a) {
    asm volatile("ldmatrix.sync.aligned.m8n8.x4.shared.b16 {%0,%1,%2,%3}, [%4];"
                 : "=r"(r[0]), "=r"(r[1]), "=r"(r[2]), "=r"(r[3]) : "r"(a));
}
__device__ __forceinline__ void ldm4t(uint32_t* r, uint32_t a) {
    asm volatile("ldmatrix.sync.aligned.m8n8.x4.trans.shared.b16 {%0,%1,%2,%3}, [%4];"
                 : "=r"(r[0]), "=r"(r[1]), "=r"(r[2]), "=r"(r[3]) : "r"(a));
}
__device__ __forceinline__ void mma16816(float* d, const uint32_t* a, const uint32_t* b) {
    asm volatile("mma.sync.aligned.m16n8k16.row.col.f32.bf16.bf16.f32 "
                 "{%0,%1,%2,%3}, {%4,%5,%6,%7}, {%8,%9}, {%0,%1,%2,%3};"
                 : "+f"(d[0]), "+f"(d[1]), "+f"(d[2]), "+f"(d[3])
                 : "r"(a[0]), "r"(a[1]), "r"(a[2]), "r"(a[3]), "r"(b[0]), "r"(b[1]));
}

// ---------------------------------------------------------------------------
// Kernel P: one-time CW conversion + per-k constants (block = one k row)
// ---------------------------------------------------------------------------
__global__ void encnet_prep(const float* __restrict__ cw, const float* __restrict__ smth)
{
    const int k = blockIdx.x, tid = threadIdx.x;     // 128 threads
    __shared__ float red[128];
    float v = __ldg(cw + k * CDIM + tid);
    __nv_bfloat16* row = (__nv_bfloat16*)((unsigned char*)g_cwb4 + k * 272);
    row[tid] = __float2bfloat16(v);
    if (tid < 8) row[128 + tid] = __float2bfloat16(0.f);   // zero pad cols 128..135
    red[tid] = v * v;
    __syncthreads();
    for (int o = 64; o > 0; o >>= 1) { if (tid < o) red[tid] += red[tid + o]; __syncthreads(); }
    if (tid == 0) {
        float s = __ldg(smth + k);
        g_c4g[k] = make_float4(s, s * red[0], -2.f * s, 0.f);
    }
}

// ---------------------------------------------------------------------------
// Kernel A: cross GEMM (mma) + softmax (frag regs) + aggregation GEMM (mma)
// 2 CTAs/SM: phases of co-resident CTAs interleave.
// ---------------------------------------------------------------------------
__global__ void __launch_bounds__(TPB, 2) encnet_main(
    const float* __restrict__ x)
{
    extern __shared__ unsigned char smem[];
    const uint32_t sb = smem_u32(smem);
    float*  x2p = (float*)(smem + SM_X2P);
    float*  atp = (float*)(smem + SM_ATP);
    float4* c4  = (float4*)(smem + SM_C4);

    const int tid = threadIdx.x, lane = tid & 31, w = tid >> 5;
    const int chunk = blockIdx.x, b = blockIdx.y;
    const float* xg = x + (long)b * CDIM * SEQ + chunk * (SEQ / NCHUNK);

    // copy precomputed CW (bf16, final layout) + c4 into smem
    {
        float4* dst = (float4*)(smem + SM_CW);
        #pragma unroll
        for (int i = 0; i < 5; i++) {
            int idx = tid + i * TPB;
            if (idx < KDIM * 272 / 16) dst[idx] = __ldg(g_cwb4 + idx);
        }
        if (tid < KDIM) c4[tid] = __ldg(g_c4g + tid);
    }

    // ldmatrix base addresses (constant per thread)
    const int m0 = 16 * w;
    const uint32_t a1base = sb + SM_XTH +
        (uint32_t)((((lane >> 4) << 3) + (lane & 7)) * 272 + (m0 + (lane & 8)) * 2);
    const uint32_t a2base = sb + SM_XTH +
        (uint32_t)((m0 + (lane & 15)) * 272 + (lane >> 4) * 16);
    const uint32_t bcw4 = sb + SM_CW +
        (uint32_t)((lane & 7) * 272 + ((lane >> 3) & 1) * 16 + (lane >> 4) * 2176);
    const uint32_t bat4 = sb + SM_AT +
        (uint32_t)((lane & 15) * 144 + (lane >> 4) * 16);

    float acc2[8][4];
    #pragma unroll
    for (int i = 0; i < 8; i++)
        { acc2[i][0] = acc2[i][1] = acc2[i][2] = acc2[i][3] = 0.f; }
    float aAcc = 0.f;

    __syncthreads();   // CW/c4 ready

    for (int t = 0; t < NTILE; t++) {
        // ---- convert: direct LDG -> bf16 XT; x2 partials in regs ----
        {
            float4 x2a = make_float4(0.f, 0.f, 0.f, 0.f);
            const float* xt0 = xg + t * STILE;
            #pragma unroll
            for (int it = 0; it < 16; it++) {
                int cc = w + it * 8;                       // warp = full row
                float4 v = __ldg((const float4*)(xt0 + (long)cc * SEQ) + lane);
                x2a.x = fmaf(v.x, v.x, x2a.x);
                x2a.y = fmaf(v.y, v.y, x2a.y);
                x2a.z = fmaf(v.z, v.z, x2a.z);
                x2a.w = fmaf(v.w, v.w, x2a.w);
                uint32_t h0 = bf2(v.x, v.y), h1 = bf2(v.z, v.w);
                *(uint2*)(smem + SM_XTH + cc * 272 + lane * 8) = make_uint2(h0, h1);
            }
            *(float4*)(x2p + w * 128 + lane * 4) = x2a;
        }
        __syncthreads();   // XT + x2p ready

        // ---- GEMM1: cross[s=128, k=64] = Xh . CW^T ----
        float acc1[8][4];
        #pragma unroll
        for (int i = 0; i < 8; i++)
            { acc1[i][0] = acc1[i][1] = acc1[i][2] = acc1[i][3] = 0.f; }
        {
            uint32_t aH[4], bb[4];
            #pragma unroll
            for (int kc = 0; kc < 8; kc++) {
                ldm4t(aH, a1base + kc * 4352);            // 16 c-rows * 272B
                #pragma unroll
                for (int ntp = 0; ntp < 4; ntp++) {
                    ldm4(bb, bcw4 + ntp * 4352 + kc * 32);
                    mma16816(acc1[2 * ntp],     aH, bb);
                    mma16816(acc1[2 * ntp + 1], aH, bb + 2);
                }
            }
        }

        // ---- softmax on fragments (x2 summed from partials inline) ----
        {
            const int g = lane >> 2, q = lane & 3;
            const int s0r = m0 + g;
            float xa = 0.f, xb = 0.f;
            #pragma unroll
            for (int ww = 0; ww < 8; ww++) {
                xa += x2p[ww * 128 + s0r];
                xb += x2p[ww * 128 + s0r + 8];
            }
            float p0[16], p1[16];
            float mA = -3.4e38f, mB = -3.4e38f;
            #pragma unroll
            for (int nt = 0; nt < 8; nt++) {
                float4 cA = c4[8 * nt + 2 * q];
                float4 cB = c4[8 * nt + 2 * q + 1];
                p0[2*nt]   = fmaf(cA.z, acc1[nt][0], fmaf(cA.x, xa, cA.y));
                p0[2*nt+1] = fmaf(cB.z, acc1[nt][1], fmaf(cB.x, xa, cB.y));
                p1[2*nt]   = fmaf(cA.z, acc1[nt][2], fmaf(cA.x, xb, cA.y));
                p1[2*nt+1] = fmaf(cB.z, acc1[nt][3], fmaf(cB.x, xb, cB.y));
                mA = fmaxf(mA, fmaxf(p0[2*nt], p0[2*nt+1]));
                mB = fmaxf(mB, fmaxf(p1[2*nt], p1[2*nt+1]));
            }
            mA = fmaxf(mA, __shfl_xor_sync(0xffffffffu, mA, 1));
            mA = fmaxf(mA, __shfl_xor_sync(0xffffffffu, mA, 2));
            mB = fmaxf(mB, __shfl_xor_sync(0xffffffffu, mB, 1));
            mB = fmaxf(mB, __shfl_xor_sync(0xffffffffu, mB, 2));
            float sA = 0.f, sB = 0.f;
            #pragma unroll
            for (int j = 0; j < 16; j++) {
                p0[j] = __expf(p0[j] - mA); sA += p0[j];
                p1[j] = __expf(p1[j] - mB); sB += p1[j];
            }
            sA += __shfl_xor_sync(0xffffffffu, sA, 1);
            sA += __shfl_xor_sync(0xffffffffu, sA, 2);
            sB += __shfl_xor_sync(0xffffffffu, sB, 1);
            sB += __shfl_xor_sync(0xffffffffu, sB, 2);
            float iA = 1.f / sA, iB = 1.f / sB;
            #pragma unroll
            for (int nt = 0; nt < 8; nt++) {
                const int k0 = 8 * nt + 2 * q;
                float a00 = p0[2*nt] * iA, a01 = p0[2*nt+1] * iA;
                float a10 = p1[2*nt] * iB, a11 = p1[2*nt+1] * iB;
                *(uint32_t*)(smem + SM_AT + s0r * 144 + k0 * 2)       = bf2(a00, a01);
                *(uint32_t*)(smem + SM_AT + (s0r + 8) * 144 + k0 * 2) = bf2(a10, a11);
                // per-k partial sums over this warp's 16 s rows
                float v0 = a00 + a10, v1 = a01 + a11;
                v0 += __shfl_xor_sync(0xffffffffu, v0, 4);
                v1 += __shfl_xor_sync(0xffffffffu, v1, 4);
                v0 += __shfl_xor_sync(0xffffffffu, v0, 8);
                v1 += __shfl_xor_sync(0xffffffffu, v1, 8);
                v0 += __shfl_xor_sync(0xffffffffu, v0, 16);
                v1 += __shfl_xor_sync(0xffffffffu, v1, 16);
                if (g == 0) {
                    atp[w * 64 + k0]     = v0;
                    atp[w * 64 + k0 + 1] = v1;
                }
            }
        }
        __syncthreads();   // AT + atp ready

        if (tid < KDIM) {
            float a = 0.f;
            #pragma unroll
            for (int ww = 0; ww < 8; ww++) a += atp[ww * 64 + tid];
            aAcc += a;
        }

        // ---- GEMM2: e[c=128, k=64] += Xh . a ----
        {
            uint32_t aH[4], bb[4];
            #pragma unroll
            for (int kc = 0; kc < 8; kc++) {
                ldm4(aH, a2base + kc * 32);               // 16 s-elems * 2B
                #pragma unroll
                for (int ntp = 0; ntp < 4; ntp++) {
                    ldm4t(bb, bat4 + kc * 2304 + ntp * 32);
                    mma16816(acc2[2 * ntp],     aH, bb);
                    mma16816(acc2[2 * ntp + 1], aH, bb + 2);
                }
            }
        }
        __syncthreads();   // GEMM2 reads done before next tile's XT/AT rewrite
    }

    // ---- epilogue: write chunk partials ----
    {
        float* ep = g_epart + ((long)(chunk * BDIM + b) * KDIM) * CDIM;
        const int c0r = m0 + (lane >> 2), q = lane & 3;
        #pragma unroll
        for (int nt = 0; nt < 8; nt++) {
            int k0 = 8 * nt + 2 * q;
            ep[k0 * CDIM + c0r]           = acc2[nt][0];
            ep[(k0 + 1) * CDIM + c0r]     = acc2[nt][1];
            ep[k0 * CDIM + c0r + 8]       = acc2[nt][2];
            ep[(k0 + 1) * CDIM + c0r + 8] = acc2[nt][3];
        }
        if (tid < KDIM) g_Apart[(chunk * BDIM + b) * KDIM + tid] = aAcc;
    }
}

// ---------------------------------------------------------------------------
// Kernel B: reduce chunk partials, subtract A*cw, BN batch stats per k
// ---------------------------------------------------------------------------
__global__ void encnet_stats(const float* __restrict__ cw,
                             const float* __restrict__ bnw,
                             const float* __restrict__ bnb)
{
    const int k = blockIdx.x, tid = threadIdx.x;   // 256 threads
    __shared__ float Ab[BDIM];
    __shared__ float red[256];

    if (tid < BDIM) {
        float a = 0.f;
        #pragma unroll
        for (int ch = 0; ch < NCHUNK; ch++) a += g_Apart[(ch * BDIM + tid) * KDIM + k];
        Ab[tid] = a;
    }
    __syncthreads();

    float sum = 0.f, ss = 0.f;
    for (int i = tid; i < BDIM * CDIM; i += 256) {
        int bb = i >> 7, c = i & 127;
        float v = 0.f;
        #pragma unroll
        for (int ch = 0; ch < NCHUNK; ch++)
            v += g_epart[(((long)ch * BDIM + bb) * KDIM + k) * CDIM + c];
        v -= Ab[bb] * __ldg(cw + k * CDIM + c);
        g_ecorr[(bb * KDIM + k) * CDIM + c] = v;
        sum += v;
        ss = fmaf(v, v, ss);
    }
    red[tid] = sum; __syncthreads();
    for (int o = 128; o > 0; o >>= 1) { if (tid < o) red[tid] += red[tid + o]; __syncthreads(); }
    float tsum = red[0]; __syncthreads();
    red[tid] = ss; __syncthreads();
    for (int o = 128; o > 0; o >>= 1) { if (tid < o) red[tid] += red[tid + o]; __syncthreads(); }
    if (tid == 0) {
        const float n = (float)(BDIM * CDIM);
        float mean = tsum / n;
        float var = red[0] / n - mean * mean;
        float rstd = rsqrtf(var + 1e-5f);
        float g = rstd * __ldg(bnw + k);
        g_gk[k] = g;
        g_hk[k] = __ldg(bnb + k) - mean * g;
    }
}

// ---------------------------------------------------------------------------
// Kernel C1: en[b][c] = mean_k relu(bn(e))  -- wide grid (8 x 16) x 256
// ---------------------------------------------------------------------------
__global__ void encnet_fc1()
{
    const int cgrp = blockIdx.x, b = blockIdx.y;
    const int tid = threadIdx.x;
    const int cl = tid & 15, kg = tid >> 4;       // kg 0..15
    const int c = cgrp * 16 + cl;
    __shared__ float red[16][17];

    float acc = 0.f;
    const float* er = g_ecorr + ((long)b * KDIM + kg * 4) * CDIM + c;
    #pragma unroll
    for (int j = 0; j < 4; j++) {
        int k = kg * 4 + j;
        acc += fmaxf(fmaf(er[j * CDIM], __ldg(&g_gk[k]), __ldg(&g_hk[k])), 0.f);
    }
    red[kg][cl] = acc;
    __syncthreads();
    if (tid < 16) {
        float s = 0.f;
        #pragma unroll
        for (int j = 0; j < 16; j++) s += red[j][tid];
        g_en[b * CDIM + cgrp * 16 + tid] = s * (1.f / (float)KDIM);
    }
}

// ---------------------------------------------------------------------------
// Kernel C2: scale[b][cout] = sigmoid(en[b].w[cout] + bias) -- grid (128 x 16) x 128
// ---------------------------------------------------------------------------
__global__ void encnet_fc2(const float* __restrict__ fcw, const float* __restrict__ fcb)
{
    const int co = blockIdx.x, b = blockIdx.y, tid = threadIdx.x;
    __shared__ float red[128];
    red[tid] = g_en[b * CDIM + tid] * __ldg(fcw + co * CDIM + tid);
    __syncthreads();
    for (int o = 64; o > 0; o >>= 1) { if (tid < o) red[tid] += red[tid + o]; __syncthreads(); }
    if (tid == 0)
        g_scale[b * CDIM + co] = 1.f / (1.f + __expf(-(red[0] + __ldg(fcb + co))));
}

// ---------------------------------------------------------------------------
// Kernel D: out = x * scale  (memory bound; 8 independent iters -> MLP 8)
// ---------------------------------------------------------------------------
__global__ void encnet_scale(const float4* __restrict__ x4, float4* __restrict__ out4)
{
    const int i0 = blockIdx.x * 256 + threadIdx.x;   // grid 4096 x 256
    #pragma unroll
    for (int j = 0; j < 8; j++) {
        int i = i0 + j * (4096 * 256);
        float s = __ldg(&g_scale[i >> 12]);
        float4 v = __ldg(x4 + i);
        v.x *= s; v.y *= s; v.z *= s; v.w *= s;
        out4[i] = v;
    }
}

// ---------------------------------------------------------------------------
extern "C" void kernel_launch(void* const* d_in, const int* in_sizes, int n_in,
                              void* d_out, int out_size)
{
    const float* x    = (const float*)d_in[0];
    const float* cw   = (const float*)d_in[1];
    const float* smth = (const float*)d_in[2];
    const float* bnw  = (const float*)d_in[3];
    const float* bnb  = (const float*)d_in[4];
    const float* fcw  = (const float*)d_in[5];
    const float* fcb  = (const float*)d_in[6];
    float* out = (float*)d_out;

    cudaFuncSetAttribute(encnet_main, cudaFuncAttributeMaxDynamicSharedMemorySize, SMEM_BYTES);

    encnet_prep <<<KDIM, CDIM>>>(cw, smth);
    encnet_main <<<dim3(NCHUNK, BDIM), TPB, SMEM_BYTES>>>(x);
    encnet_stats<<<KDIM, 256>>>(cw, bnw, bnb);
    encnet_fc1  <<<dim3(8, BDIM), 256>>>();
    encnet_fc2  <<<dim3(CDIM, BDIM), 128>>>(fcw, fcb);
    encnet_scale<<<4096, 256>>>((const float4*)x, (float4*)out);
}